// round 17
// baseline (speedup 1.0000x reference)
#include <cuda_runtime.h>
#include <cstdint>
#include <cstddef>

#define DI __device__ __forceinline__

constexpr int Bn = 8, Nn = 1024, Dn = 256, Hn = 4;
constexpr int ROWS = Bn * Nn;  // 8192
constexpr int IB = 8;          // rows per mega CTA
constexpr int SCAP = 128;      // survivor cap
constexpr int LCAP = 80;       // softmax list cap

// -------- scratch (static device globals: allocation-free) --------
__device__ float g_Q[ROWS * Dn];
__device__ float g_K[ROWS * Dn];
__device__ float g_V[ROWS * Dn];
__device__ float g_M[ROWS * Dn];

// -------- packed f32x2 helpers --------
DI unsigned long long pack2(float lo, float hi) {
    unsigned long long r;
    asm("mov.b64 %0, {%1, %2};" : "=l"(r) : "f"(lo), "f"(hi));
    return r;
}
DI void fma2(unsigned long long& d, unsigned long long a, unsigned long long b) {
    asm("fma.rn.f32x2 %0, %1, %2, %0;" : "+l"(d) : "l"(a), "l"(b));
}
DI float2 unpack2(unsigned long long v) {
    float lo, hi;
    asm("mov.b64 {%0, %1}, %2;" : "=f"(lo), "=f"(hi) : "l"(v));
    return make_float2(lo, hi);
}

// monotone float->uint mapping (order-preserving)
DI unsigned mapf(float x) {
    unsigned b = __float_as_uint(x);
    return (b & 0x80000000u) ? ~b : (b | 0x80000000u);
}
DI float invmap(unsigned u) {
    unsigned b = (u & 0x80000000u) ? (u & 0x7FFFFFFFu) : ~u;
    return __uint_as_float(b);
}

// inner 8x8 f32x2 FMA block (for the projection GEMMs)
#define MMA_KK(AS, BS)                                                        \
    {                                                                         \
        float4 a0 = *(const float4*)&AS[trow];                                \
        float4 a1 = *(const float4*)&AS[trow + 4];                            \
        ulonglong2 b0 = *(const ulonglong2*)&BS[c0];                          \
        ulonglong2 b1 = *(const ulonglong2*)&BS[c0 + 64];                     \
        unsigned long long ad[8];                                             \
        ad[0] = pack2(a0.x, a0.x); ad[1] = pack2(a0.y, a0.y);                 \
        ad[2] = pack2(a0.z, a0.z); ad[3] = pack2(a0.w, a0.w);                 \
        ad[4] = pack2(a1.x, a1.x); ad[5] = pack2(a1.y, a1.y);                 \
        ad[6] = pack2(a1.z, a1.z); ad[7] = pack2(a1.w, a1.w);                 \
        _Pragma("unroll")                                                     \
        for (int i_ = 0; i_ < 8; ++i_) {                                      \
            fma2(acc[i_][0], ad[i_], b0.x);                                   \
            fma2(acc[i_][1], ad[i_], b0.y);                                   \
            fma2(acc[i_][2], ad[i_], b1.x);                                   \
            fma2(acc[i_][3], ad[i_], b1.y);                                   \
        }                                                                     \
    }

// ============================================================================
// Projection GEMM (R13): 64x128 tile, 128 thr, 8x8/thread, BK=8 dbl-buffered.
// z selects (W,b,C). C = A @ W^T + b.
// ============================================================================
__global__ void __launch_bounds__(128, 4) gemm_qkv_kernel(
    const float* __restrict__ A,
    const float* __restrict__ W0, const float* __restrict__ W1, const float* __restrict__ W2,
    const float* __restrict__ b0_, const float* __restrict__ b1_, const float* __restrict__ b2_,
    float* __restrict__ C0, float* __restrict__ C1, float* __restrict__ C2)
{
    __shared__ __align__(16) float As[2][8][68];
    __shared__ __align__(16) float Bs[2][8][132];

    const int z = blockIdx.z;
    const float* W    = (z == 0) ? W0  : (z == 1) ? W1  : W2;
    const float* bias = (z == 0) ? b0_ : (z == 1) ? b1_ : b2_;
    float*       C    = (z == 0) ? C0  : (z == 1) ? C1  : C2;

    const int tid  = threadIdx.x;
    const int m0   = blockIdx.y * 64;
    const int n0   = blockIdx.x * 128;
    const int trow = (tid >> 4) << 3;
    const int c0   = (tid & 15) << 2;
    const int r    = tid >> 1;
    const int q    = (tid & 1) << 2;

    const float* Ap  = A + (size_t)(m0 + r) * 256 + q;
    const float* Wp0 = W + (size_t)(n0 + r) * 256 + q;
    const float* Wp1 = W + (size_t)(n0 + r + 64) * 256 + q;

    unsigned long long acc[8][4];
#pragma unroll
    for (int i = 0; i < 8; ++i)
#pragma unroll
        for (int p = 0; p < 4; ++p) acc[i][p] = 0ULL;

    {
        float4 av  = *(const float4*)Ap;
        float4 wv0 = *(const float4*)Wp0;
        float4 wv1 = *(const float4*)Wp1;
        As[0][q + 0][r] = av.x;  As[0][q + 1][r] = av.y;
        As[0][q + 2][r] = av.z;  As[0][q + 3][r] = av.w;
        Bs[0][q + 0][r] = wv0.x; Bs[0][q + 1][r] = wv0.y;
        Bs[0][q + 2][r] = wv0.z; Bs[0][q + 3][r] = wv0.w;
        Bs[0][q + 0][r + 64] = wv1.x; Bs[0][q + 1][r + 64] = wv1.y;
        Bs[0][q + 2][r + 64] = wv1.z; Bs[0][q + 3][r + 64] = wv1.w;
    }
    __syncthreads();

#pragma unroll 2
    for (int it = 0; it < 32; ++it) {
        const int cur = it & 1;
        float4 avn, wvn0, wvn1;
        if (it < 31) {
            avn  = *(const float4*)(Ap  + (it + 1) * 8);
            wvn0 = *(const float4*)(Wp0 + (it + 1) * 8);
            wvn1 = *(const float4*)(Wp1 + (it + 1) * 8);
        }
#pragma unroll
        for (int kk = 0; kk < 8; ++kk) {
            MMA_KK(As[cur][kk], Bs[cur][kk]);
        }
        if (it < 31) {
            const int nxt = cur ^ 1;
            As[nxt][q + 0][r] = avn.x;  As[nxt][q + 1][r] = avn.y;
            As[nxt][q + 2][r] = avn.z;  As[nxt][q + 3][r] = avn.w;
            Bs[nxt][q + 0][r] = wvn0.x; Bs[nxt][q + 1][r] = wvn0.y;
            Bs[nxt][q + 2][r] = wvn0.z; Bs[nxt][q + 3][r] = wvn0.w;
            Bs[nxt][q + 0][r + 64] = wvn1.x; Bs[nxt][q + 1][r + 64] = wvn1.y;
            Bs[nxt][q + 2][r + 64] = wvn1.z; Bs[nxt][q + 3][r + 64] = wvn1.w;
            __syncthreads();
        }
    }

    float4 bb0 = *(const float4*)&bias[n0 + c0];
    float4 bb1 = *(const float4*)&bias[n0 + c0 + 64];
#pragma unroll
    for (int i = 0; i < 8; ++i) {
        int m = m0 + trow + i;
        float2 v0 = unpack2(acc[i][0]), v1 = unpack2(acc[i][1]);
        float2 v2 = unpack2(acc[i][2]), v3 = unpack2(acc[i][3]);
        float4 o0 = make_float4(v0.x + bb0.x, v0.y + bb0.y, v1.x + bb0.z, v1.y + bb0.w);
        float4 o1 = make_float4(v2.x + bb1.x, v2.y + bb1.y, v3.x + bb1.z, v3.y + bb1.w);
        *(float4*)&C[(size_t)m * 256 + n0 + c0]      = o0;
        *(float4*)&C[(size_t)m * 256 + n0 + c0 + 64] = o1;
    }
}

// ============================================================================
// MEGA kernel: scores + exact top-k + sparse softmax + adjacency + attn@V
// for an 8-row block (all 4 heads) in ONE kernel. No g_S materialization.
//
// Dynamic smem layout (floats):
//   [0,      32768)  sc[4][8][1024]        (scores; later overlaid by adj[8][1024])
//   [32768,  49664)  kb: per warp [2][8][132]  (K staging; later overlaid by lists)
//   [49664,  51712)  qs[(h*64+k)*8 + i]    (Q block, k-major transposed)
// Overlays (post-GEMM, after __syncthreads):
//   lists:  jl int[32][LCAP] @32768, av float[32][LCAP] @+32*LCAP
//   surv:   su uint[8][SCAP] @+64*LCAP, si int[8][SCAP] after su
// ============================================================================
constexpr int SC_F = 0;
constexpr int KB_F = 32768;
constexpr int QS_F = 49664;
constexpr int SMEM_F = 51712;
constexpr int MEGA_SMEM = SMEM_F * 4;  // 206848 bytes

__global__ void __launch_bounds__(256, 1) mega_attn_kernel(
    const float* __restrict__ td, const int* __restrict__ topk_ptr,
    float* __restrict__ out_adj)
{
    extern __shared__ __align__(16) float sm[];
    const int tid  = threadIdx.x;
    const int w    = tid >> 5;
    const int lane = tid & 31;
    const int b    = blockIdx.x >> 7;
    const int i0   = (blockIdx.x & 127) * IB;
    const int h    = w & 3;        // GEMM: head of this warp
    const int jh   = w >> 2;       // GEMM: j-half (0/1)

    float* sc = sm + SC_F;                    // [4][8][1024]
    float* kb = sm + KB_F + w * 2112;         // per-warp [2][8][132]
    float* qs = sm + QS_F;                    // [(h*64+k)*8 + i]

    // ---- stage Q block: 4 heads x 8 rows x 64 k, k-major transposed ----
    {
        const int i = w;              // 0..7
        const int c = lane * 8;       // 0..248
        const float* qp = g_Q + ((size_t)(b * Nn + i0 + i)) * 256 + c;
        float4 q0 = *(const float4*)qp;
        float4 q1 = *(const float4*)(qp + 4);
        const int hh = c >> 6, k = c & 63;
        float* dst = qs + ((hh * 64 + k) * 8 + i);
        dst[0]  = q0.x; dst[8]  = q0.y; dst[16] = q0.z; dst[24] = q0.w;
        dst[32] = q1.x; dst[40] = q1.y; dst[48] = q1.z; dst[56] = q1.w;
    }
    __syncthreads();

    // ---- GEMM: scores[h][i][j] for j in [jh*512, jh*512+512) ----
    const size_t kbase = ((size_t)b * Nn) * 256 + h * 64;
    for (int jt = 0; jt < 4; ++jt) {
        const int j0t = jh * 512 + jt * 128;
        unsigned long long acc[8][2];
#pragma unroll
        for (int i = 0; i < 8; ++i) { acc[i][0] = 0ULL; acc[i][1] = 0ULL; }

        float4 ld[4][2];
        // prologue: chunk 0
#pragma unroll
        for (int r = 0; r < 4; ++r) {
            const float* kp = g_K + kbase + (size_t)(j0t + lane + 32 * r) * 256;
            ld[r][0] = *(const float4*)kp;
            ld[r][1] = *(const float4*)(kp + 4);
        }
#pragma unroll
        for (int r = 0; r < 4; ++r) {
            const int jj = lane + 32 * r;
            kb[0 * 132 + jj] = ld[r][0].x; kb[1 * 132 + jj] = ld[r][0].y;
            kb[2 * 132 + jj] = ld[r][0].z; kb[3 * 132 + jj] = ld[r][0].w;
            kb[4 * 132 + jj] = ld[r][1].x; kb[5 * 132 + jj] = ld[r][1].y;
            kb[6 * 132 + jj] = ld[r][1].z; kb[7 * 132 + jj] = ld[r][1].w;
        }
        __syncwarp();

        for (int kc = 0; kc < 8; ++kc) {
            const int cur = kc & 1;
            if (kc < 7) {
#pragma unroll
                for (int r = 0; r < 4; ++r) {
                    const float* kp = g_K + kbase +
                        (size_t)(j0t + lane + 32 * r) * 256 + (kc + 1) * 8;
                    ld[r][0] = *(const float4*)kp;
                    ld[r][1] = *(const float4*)(kp + 4);
                }
            }
#pragma unroll
            for (int kk = 0; kk < 8; ++kk) {
                const float* ap = qs + (h * 64 + kc * 8 + kk) * 8;
                float4 a0 = *(const float4*)ap;
                float4 a1 = *(const float4*)(ap + 4);
                ulonglong2 bv = *(const ulonglong2*)&kb[cur * 1056 + kk * 132 + lane * 4];
                unsigned long long ad[8];
                ad[0] = pack2(a0.x, a0.x); ad[1] = pack2(a0.y, a0.y);
                ad[2] = pack2(a0.z, a0.z); ad[3] = pack2(a0.w, a0.w);
                ad[4] = pack2(a1.x, a1.x); ad[5] = pack2(a1.y, a1.y);
                ad[6] = pack2(a1.z, a1.z); ad[7] = pack2(a1.w, a1.w);
#pragma unroll
                for (int i = 0; i < 8; ++i) {
                    fma2(acc[i][0], ad[i], bv.x);
                    fma2(acc[i][1], ad[i], bv.y);
                }
            }
            if (kc < 7) {
                const int nb = (cur ^ 1) * 1056;
#pragma unroll
                for (int r = 0; r < 4; ++r) {
                    const int jj = lane + 32 * r;
                    kb[nb + 0 * 132 + jj] = ld[r][0].x; kb[nb + 1 * 132 + jj] = ld[r][0].y;
                    kb[nb + 2 * 132 + jj] = ld[r][0].z; kb[nb + 3 * 132 + jj] = ld[r][0].w;
                    kb[nb + 4 * 132 + jj] = ld[r][1].x; kb[nb + 5 * 132 + jj] = ld[r][1].y;
                    kb[nb + 6 * 132 + jj] = ld[r][1].z; kb[nb + 7 * 132 + jj] = ld[r][1].w;
                }
                __syncwarp();
            }
        }

        // epilogue: sc = 0.125*acc - 0.1*td
        const int j = j0t + lane * 4;
#pragma unroll
        for (int i = 0; i < 8; ++i) {
            float4 t = __ldcs((const float4*)(td + ((size_t)(b * Nn + i0 + i)) * Nn + j));
            float2 p0 = unpack2(acc[i][0]), p1 = unpack2(acc[i][1]);
            float4 o = make_float4(p0.x * 0.125f - 0.1f * t.x,
                                   p0.y * 0.125f - 0.1f * t.y,
                                   p1.x * 0.125f - 0.1f * t.z,
                                   p1.y * 0.125f - 0.1f * t.w);
            *(float4*)&sc[(h * 8 + i) * 1024 + j] = o;
        }
    }
    __syncthreads();   // all scores in smem; K buffers now dead

    // ---- overlays ----
    int*      jlA = (int*)(sm + KB_F);                       // [32][LCAP]
    float*    avA = sm + KB_F + 32 * LCAP;                   // [32][LCAP]
    unsigned* suW = (unsigned*)(sm + KB_F + 64 * LCAP) + w * SCAP;
    int*      siW = (int*)(sm + KB_F + 64 * LCAP + 8 * SCAP) + w * SCAP;

    int kv = *topk_ptr;
    if (kv > Nn) kv = Nn;
    if (kv < 1)  kv = 1;

    int cnts[4];

    // ---- selection + softmax: warp w owns row i=w, heads serial ----
    for (int hh = 0; hh < 4; ++hh) {
        const float* row = sc + (hh * 8 + w) * 1024;
        const int pp = w * 4 + hh;
        int*   jlp = jlA + pp * LCAP;
        float* avp = avA + pp * LCAP;
        int c2;
        float mx;
        {
            unsigned lmax = 0u;
#pragma unroll
            for (int e = 0; e < 32; ++e)
                lmax = umax(lmax, mapf(row[e * 32 + lane]));
            const unsigned T0 = __reduce_min_sync(0xffffffffu, lmax);
            const unsigned Mx = __reduce_max_sync(0xffffffffu, lmax);
            mx = invmap(Mx);

            int base = 0;
#pragma unroll
            for (int e = 0; e < 32; ++e) {
                int j = e * 32 + lane;
                unsigned u = mapf(row[j]);
                bool p = (u >= T0);
                unsigned m = __ballot_sync(0xffffffffu, p);
                if (p) {
                    int pos = base + __popc(m & ((1u << lane) - 1u));
                    if (pos < SCAP) { suW[pos] = u; siW[pos] = j; }
                }
                base += __popc(m);
            }
            const int cnt = base;
            __syncwarp();

            if (kv <= 32 && cnt <= SCAP) {
                unsigned v0 = (lane      < cnt) ? suW[lane]      : 0u;
                unsigned v1 = (lane + 32 < cnt) ? suW[lane + 32] : 0u;
                unsigned v2 = (lane + 64 < cnt) ? suW[lane + 64] : 0u;
                unsigned v3 = (lane + 96 < cnt) ? suW[lane + 96] : 0u;
                unsigned kthU = 0, pref = 0; bool got = false;
                for (int bit = 31; bit >= 0; --bit) {
                    unsigned cand = pref | (1u << bit);
                    unsigned c = (v0 >= cand) + (v1 >= cand) + (v2 >= cand) + (v3 >= cand);
                    c = __reduce_add_sync(0xffffffffu, c);
                    if (c == (unsigned)kv) {
                        unsigned mn = 0xFFFFFFFFu;
                        if (v0 >= cand) mn = umin(mn, v0);
                        if (v1 >= cand) mn = umin(mn, v1);
                        if (v2 >= cand) mn = umin(mn, v2);
                        if (v3 >= cand) mn = umin(mn, v3);
                        kthU = __reduce_min_sync(0xffffffffu, mn);
                        got = true; break;
                    }
                    if (c > (unsigned)kv) pref = cand;
                }
                if (!got) kthU = pref;

                unsigned vv[4] = { v0, v1, v2, v3 };
                int b2 = 0;
#pragma unroll
                for (int e = 0; e < 4; ++e) {
                    int idx = lane + 32 * e;
                    bool p = (idx < cnt) && (vv[e] >= kthU);
                    unsigned m = __ballot_sync(0xffffffffu, p);
                    if (p) {
                        int pos = b2 + __popc(m & ((1u << lane) - 1u));
                        if (pos < LCAP) { jlp[pos] = siW[idx]; avp[pos] = invmap(vv[e]); }
                    }
                    b2 += __popc(m);
                }
                c2 = (b2 > LCAP) ? LCAP : b2;
            } else {
                unsigned kthU = 0, pref = 0; bool got = false;
                for (int bit = 31; bit >= 0; --bit) {
                    unsigned cand = pref | (1u << bit);
                    unsigned c = 0;
#pragma unroll
                    for (int e = 0; e < 32; ++e)
                        c += (mapf(row[e * 32 + lane]) >= cand) ? 1u : 0u;
                    c = __reduce_add_sync(0xffffffffu, c);
                    if (c == (unsigned)kv) {
                        unsigned mn = 0xFFFFFFFFu;
#pragma unroll
                        for (int e = 0; e < 32; ++e) {
                            unsigned u = mapf(row[e * 32 + lane]);
                            if (u >= cand) mn = umin(mn, u);
                        }
                        kthU = __reduce_min_sync(0xffffffffu, mn);
                        got = true; break;
                    }
                    if (c > (unsigned)kv) pref = cand;
                }
                if (!got) kthU = pref;
                const float kth = invmap(kthU);

                int b2 = 0;
#pragma unroll
                for (int rr = 0; rr < 32; ++rr) {
                    int j = rr * 32 + lane;
                    float s = row[j];
                    bool p = (s >= kth);
                    unsigned m = __ballot_sync(0xffffffffu, p);
                    if (p) {
                        int pos = b2 + __popc(m & ((1u << lane) - 1u));
                        if (pos < LCAP) { jlp[pos] = j; avp[pos] = s; }
                    }
                    b2 += __popc(m);
                }
                c2 = (b2 > LCAP) ? LCAP : b2;
            }
        }
        __syncwarp();

        // softmax over survivors (normalized in place)
        float lsum = 0.f;
        for (int l = lane; l < c2; l += 32) {
            float e = __expf(avp[l] - mx);
            avp[l] = e;
            lsum += e;
        }
#pragma unroll
        for (int o = 16; o; o >>= 1) lsum += __shfl_xor_sync(0xffffffffu, lsum, o);
        const float inv = 1.f / lsum;   // max survives -> lsum >= 1
        for (int l = lane; l < c2; l += 32) avp[l] *= inv;
        cnts[hh] = c2;
    }
    __syncthreads();   // scores region now dead

    // ---- adjacency accumulate (overlay sc region) ----
    float* adj = sm;   // [8][1024]
#pragma unroll
    for (int r = 0; r < 8; ++r)
        ((float4*)adj)[tid + 256 * r] = make_float4(0.f, 0.f, 0.f, 0.f);
    __syncthreads();

    // ---- scatter + V gather: warp w owns row i=w ----
    for (int hh = 0; hh < 4; ++hh) {
        const int pp = w * 4 + hh;
        const int*   jlp = jlA + pp * LCAP;
        const float* avp = avA + pp * LCAP;
        const int c2 = cnts[hh];

        for (int l = lane; l < c2; l += 32)
            atomicAdd(&adj[w * 1024 + jlp[l]], 0.25f * avp[l]);

        const float2* vb2 = (const float2*)(g_V + ((size_t)b * Nn) * 256 + hh * 64);
        float ax = 0.f, ay = 0.f;
        int l = 0;
        for (; l + 8 <= c2; l += 8) {
            float2 x0 = vb2[(size_t)jlp[l]     * 128 + lane];
            float2 x1 = vb2[(size_t)jlp[l + 1] * 128 + lane];
            float2 x2 = vb2[(size_t)jlp[l + 2] * 128 + lane];
            float2 x3 = vb2[(size_t)jlp[l + 3] * 128 + lane];
            float2 x4 = vb2[(size_t)jlp[l + 4] * 128 + lane];
            float2 x5 = vb2[(size_t)jlp[l + 5] * 128 + lane];
            float2 x6 = vb2[(size_t)jlp[l + 6] * 128 + lane];
            float2 x7 = vb2[(size_t)jlp[l + 7] * 128 + lane];
            float a0 = avp[l],     a1 = avp[l + 1], a2 = avp[l + 2], a3 = avp[l + 3];
            float a4 = avp[l + 4], a5 = avp[l + 5], a6 = avp[l + 6], a7 = avp[l + 7];
            ax = fmaf(a0, x0.x, ax); ay = fmaf(a0, x0.y, ay);
            ax = fmaf(a1, x1.x, ax); ay = fmaf(a1, x1.y, ay);
            ax = fmaf(a2, x2.x, ax); ay = fmaf(a2, x2.y, ay);
            ax = fmaf(a3, x3.x, ax); ay = fmaf(a3, x3.y, ay);
            ax = fmaf(a4, x4.x, ax); ay = fmaf(a4, x4.y, ay);
            ax = fmaf(a5, x5.x, ax); ay = fmaf(a5, x5.y, ay);
            ax = fmaf(a6, x6.x, ax); ay = fmaf(a6, x6.y, ay);
            ax = fmaf(a7, x7.x, ax); ay = fmaf(a7, x7.y, ay);
        }
        for (; l < c2; ++l) {
            float2 x = vb2[(size_t)jlp[l] * 128 + lane];
            float a = avp[l];
            ax = fmaf(a, x.x, ax); ay = fmaf(a, x.y, ay);
        }
        float2* mrow2 = (float2*)(g_M + ((size_t)(b * Nn + i0 + w)) * 256 + hh * 64);
        mrow2[lane] = make_float2(ax, ay);
    }
    __syncthreads();

    // ---- adjacency writeout: 8 rows x 1024 floats ----
#pragma unroll
    for (int r = 0; r < 8; ++r) {
        int g  = tid + 256 * r;
        int i  = g >> 8;
        int c4 = g & 255;
        float4 vq = ((const float4*)adj)[g];
        __stcs((float4*)(out_adj + ((size_t)(b * Nn + i0 + i)) * Nn) + c4, vq);
    }
}

// ============================================================================
extern "C" void kernel_launch(void* const* d_in, const int* in_sizes, int n_in,
                              void* d_out, int out_size)
{
    const float* h_in = (const float*)d_in[0];
    const float* td   = (const float*)d_in[1];
    const float* Wq   = (const float*)d_in[2];
    const float* bq   = (const float*)d_in[3];
    const float* Wk   = (const float*)d_in[4];
    const float* bk   = (const float*)d_in[5];
    const float* Wv   = (const float*)d_in[6];
    const float* bv   = (const float*)d_in[7];
    const float* Wo   = (const float*)d_in[8];
    const float* bo   = (const float*)d_in[9];
    const int*   tk   = (const int*)d_in[10];

    float* out_adj = (float*)d_out;
    float* out_msg = out_adj + (size_t)Bn * Nn * Nn;

    float *q, *k, *v, *m;
    cudaGetSymbolAddress((void**)&q, g_Q);
    cudaGetSymbolAddress((void**)&k, g_K);
    cudaGetSymbolAddress((void**)&v, g_V);
    cudaGetSymbolAddress((void**)&m, g_M);

    cudaFuncSetAttribute(mega_attn_kernel,
                         cudaFuncAttributeMaxDynamicSharedMemorySize, MEGA_SMEM);

    gemm_qkv_kernel<<<dim3(2, 128, 3), 128>>>(h_in, Wq, Wk, Wv, bq, bk, bv, q, k, v);
    mega_attn_kernel<<<Bn * (Nn / IB), 256, MEGA_SMEM>>>(td, tk, out_adj);
    gemm_qkv_kernel<<<dim3(2, 128, 1), 128>>>(m, Wo, Wo, Wo, bo, bo, bo,
                                              out_msg, out_msg, out_msg);
}